// round 2
// baseline (speedup 1.0000x reference)
#include <cuda_runtime.h>
#include <math.h>

// ---------------------------------------------------------------------------
// MultiCrossAlign: 3-scale windowed cross-attention + attention transfer +
// fusion convs. All fp32. Scratch in __device__ globals (no allocations).
// ---------------------------------------------------------------------------

static const int ATTN_SMEM = (6*64*65 + 64 + 900 + 64) * (int)sizeof(float); // 103,952 B

__device__ float g_mask  [4*256*256];       // per-scale exposure mask (reused)
__device__ float g_att3m [256*4096];        // head-mean attention, scale 3
__device__ float g_att2m [1024*4096];       // head-mean attention, scale 2
__device__ float g_aligned[4*64*256*256];   // aligned feature (max scale)
__device__ float g_up    [4*64*256*256];    // upsampled feature
__device__ float g_atrans[4*64*256*256];    // attention-transferred feature
__device__ float g_feat  [4*64*128*128];    // small intermediate (<=128^2)

// ---------------------------------------------------------------------------
// mask[b,y,x] = mean_c( ref[b,c,y,x] > 0.95 ? 0 : 1 )
// ---------------------------------------------------------------------------
__global__ void mask_kernel(const float* __restrict__ ref, float* __restrict__ mask,
                            int total, int HW) {
    int idx = blockIdx.x * 256 + threadIdx.x;
    if (idx >= total) return;
    int b = idx / HW;
    int p = idx - b * HW;
    const float* r = ref + (long long)b * 64 * HW + p;
    float s = 0.f;
    #pragma unroll
    for (int c = 0; c < 64; c++) s += (r[(long long)c * HW] > 0.95f) ? 0.f : 1.f;
    mask[idx] = s * (1.f / 64.f);
}

// ---------------------------------------------------------------------------
// 64x64x64 GEMM in shared memory: out[n][c] = sum_cc in[n][cc]*w[c][cc] + b[c],
// scaled. Weight staged transposed (s_w[cc][c], stride 65) so the inner loop
// is: 4 conflict-free activation loads + 4 broadcast weight loads per 16 FMA.
// ---------------------------------------------------------------------------
__device__ __forceinline__ void gemm64(const float* __restrict__ s_in,
                                       const float* __restrict__ gw,
                                       const float* __restrict__ gb,
                                       float* s_w, float* s_bvec, float* s_out,
                                       int tid, float scale) {
    __syncthreads();
    #pragma unroll 4
    for (int idx = tid; idx < 4096; idx += 256) {
        int c = idx >> 6, cc = idx & 63;
        s_w[cc * 65 + c] = gw[idx];          // transpose on store
    }
    if (tid < 64) s_bvec[tid] = gb[tid];
    __syncthreads();
    const int tn = tid & 15, tc = tid >> 4;
    float acc[4][4];
    #pragma unroll
    for (int j = 0; j < 4; j++) {
        float bv = s_bvec[tc + 16 * j];
        #pragma unroll
        for (int i = 0; i < 4; i++) acc[i][j] = bv;
    }
    #pragma unroll 8
    for (int cc = 0; cc < 64; cc++) {
        float xv[4], wv[4];
        #pragma unroll
        for (int i = 0; i < 4; i++) xv[i] = s_in[(tn + 16 * i) * 65 + cc];
        #pragma unroll
        for (int j = 0; j < 4; j++) wv[j] = s_w[cc * 65 + tc + 16 * j];
        #pragma unroll
        for (int i = 0; i < 4; i++)
            #pragma unroll
            for (int j = 0; j < 4; j++) acc[i][j] = fmaf(xv[i], wv[j], acc[i][j]);
    }
    #pragma unroll
    for (int i = 0; i < 4; i++)
        #pragma unroll
        for (int j = 0; j < 4; j++)
            s_out[(tn + 16 * i) * 65 + tc + 16 * j] = acc[i][j] * scale;
    __syncthreads();
}

// ---------------------------------------------------------------------------
// Fused windowed cross-attention. One CTA per 8x8 window, 256 threads.
// Thread (h = tid/64, n = tid%64) owns one attention row in registers.
// Writes aligned output (NCHW) and (optionally) the head-mean attention.
// ---------------------------------------------------------------------------
template<bool WRITE_ATT>
__global__ __launch_bounds__(256, 1)
void attn_kernel(const float* __restrict__ ref, const float* __restrict__ ta,
                 const float* __restrict__ mask,
                 const float* __restrict__ qw, const float* __restrict__ qb,
                 const float* __restrict__ kw, const float* __restrict__ kb,
                 const float* __restrict__ vw, const float* __restrict__ vb,
                 const float* __restrict__ pw, const float* __restrict__ pb,
                 const float* __restrict__ btab,
                 float* __restrict__ outp, float* __restrict__ attm,
                 int H, int W) {
    extern __shared__ float sm[];
    float* s_x    = sm;               // masked ref window [64][65]; later: attn@V output
    float* s_y    = s_x + 64 * 65;    // ta window
    float* s_q    = s_y + 64 * 65;    // Q; later: proj output staging
    float* s_k    = s_q + 64 * 65;
    float* s_v    = s_k + 64 * 65;
    float* s_w    = s_v + 64 * 65;    // weight staging; also mean-att accumulator
    float* s_mw   = s_w + 64 * 65;    // [64] window mask
    float* s_bias = s_mw + 64;        // [225][4] relative bias table
    float* s_bvec = s_bias + 900;     // [64] bias vector

    const int tid = threadIdx.x;
    const int nwx = W >> 3;
    const int winsb = (H >> 3) * nwx;
    const int wi = blockIdx.x;
    const int b = wi / winsb;
    const int rr = wi - b * winsb;
    const int y0 = (rr / nwx) << 3;
    const int x0 = (rr - (rr / nwx) * nwx) << 3;
    const long long HW = (long long)H * W;
    const float* refb = ref + (long long)b * 64 * HW;
    const float* tab  = ta + (long long)b * 64 * HW;
    const float* mb   = mask + (long long)b * HW;

    #pragma unroll 4
    for (int idx = tid; idx < 4096; idx += 256) {
        int c = idx >> 6, n = idx & 63;
        int y = y0 + (n >> 3), x = x0 + (n & 7);
        long long g = (long long)c * HW + y * W + x;
        float m = mb[y * W + x];
        s_x[n * 65 + c] = refb[g] * m;    // x = ref * mask
        s_y[n * 65 + c] = tab[g];
    }
    if (tid < 64) s_mw[tid] = mb[(y0 + (tid >> 3)) * W + x0 + (tid & 7)];
    for (int i = tid; i < 900; i += 256) s_bias[i] = btab[i];

    gemm64(s_x, qw, qb, s_w, s_bvec, s_q, tid, 0.25f);  // scale = hd^-0.5
    gemm64(s_y, kw, kb, s_w, s_bvec, s_k, tid, 1.f);
    gemm64(s_y, vw, vb, s_w, s_bvec, s_v, tid, 1.f);

    const int h = tid >> 6;
    const int n = tid & 63;
    float qr[16];
    #pragma unroll
    for (int d = 0; d < 16; d++) qr[d] = s_q[n * 65 + h * 16 + d];
    const float mwn = s_mw[n];
    const int yn = n >> 3, xn = n & 7;
    float a[64];
    #pragma unroll
    for (int m = 0; m < 64; m++) {
        float s = 0.f;
        #pragma unroll
        for (int d = 0; d < 16; d++) s = fmaf(qr[d], s_k[m * 65 + h * 16 + d], s);
        int ym = m >> 3, xm = m & 7;
        int rel = (yn - ym + 7) * 15 + (xn - xm + 7);
        a[m] = s * (mwn * s_mw[m]) + s_bias[rel * 4 + h];
    }
    // softmax over the register row
    float mx = a[0];
    #pragma unroll
    for (int m = 1; m < 64; m++) mx = fmaxf(mx, a[m]);
    float ssum = 0.f;
    #pragma unroll
    for (int m = 0; m < 64; m++) { a[m] = __expf(a[m] - mx); ssum += a[m]; }
    float inv = 1.f / ssum;
    #pragma unroll
    for (int m = 0; m < 64; m++) a[m] *= inv;

    if (WRITE_ATT) {
        // accumulate head-mean attention into s_w (serialized over heads)
        #pragma unroll
        for (int hh = 0; hh < 4; hh++) {
            if (h == hh) {
                if (hh == 0) {
                    #pragma unroll
                    for (int m = 0; m < 64; m++) s_w[n * 65 + m] = 0.25f * a[m];
                } else {
                    #pragma unroll
                    for (int m = 0; m < 64; m++) s_w[n * 65 + m] += 0.25f * a[m];
                }
            }
            __syncthreads();
        }
        float* ap = attm + (long long)wi * 4096;
        #pragma unroll 4
        for (int idx = tid; idx < 4096; idx += 256)
            ap[idx] = s_w[(idx >> 6) * 65 + (idx & 63)];
    }

    // out_h = attn @ V_h (16 values per thread)
    float o16[16];
    #pragma unroll
    for (int d = 0; d < 16; d++) o16[d] = 0.f;
    #pragma unroll
    for (int m = 0; m < 64; m++) {
        float am = a[m];
        #pragma unroll
        for (int d = 0; d < 16; d++) o16[d] = fmaf(am, s_v[m * 65 + h * 16 + d], o16[d]);
    }
    #pragma unroll
    for (int d = 0; d < 16; d++) s_x[n * 65 + h * 16 + d] = o16[d];

    gemm64(s_x, pw, pb, s_w, s_bvec, s_q, tid, 1.f);    // output projection

    float* ob = outp + (long long)b * 64 * HW;
    #pragma unroll 4
    for (int idx = tid; idx < 4096; idx += 256) {
        int c = idx >> 6, n2 = idx & 63;
        ob[(long long)c * HW + (y0 + (n2 >> 3)) * W + x0 + (n2 & 7)] = s_q[n2 * 65 + c];
    }
}

// ---------------------------------------------------------------------------
// Attention transfer: out_window = mean_h(att) @ reshaped ta window.
// One CTA per 16x16 window; 4 GEMMs of 64x64x64 (one per (pi,pj) sub-pixel).
// ---------------------------------------------------------------------------
__global__ __launch_bounds__(256)
void atrans_kernel(const float* __restrict__ ta, const float* __restrict__ attm,
                   float* __restrict__ outp, int H, int W) {
    __shared__ float s_a[64 * 65];
    __shared__ float s_t[64 * 65];
    const int tid = threadIdx.x;
    const int nwx = W >> 4;
    const int winsb = (H >> 4) * nwx;
    const int wi = blockIdx.x;
    const int b = wi / winsb;
    const int rr = wi - b * winsb;
    const int y0 = (rr / nwx) << 4;
    const int x0 = (rr - (rr / nwx) * nwx) << 4;
    const long long HW = (long long)H * W;
    const float* tb = ta + (long long)b * 64 * HW;

    for (int idx = tid; idx < 4096; idx += 256)
        s_a[(idx >> 6) * 65 + (idx & 63)] = attm[(long long)wi * 4096 + idx];

    const int tn = tid & 15, tc = tid >> 4;
    #pragma unroll
    for (int pi = 0; pi < 2; pi++) {
        #pragma unroll
        for (int pj = 0; pj < 2; pj++) {
            __syncthreads();
            for (int idx = tid; idx < 4096; idx += 256) {
                int c = idx >> 6, m = idx & 63;
                int gy = y0 + ((m >> 3) << 1) + pi;
                int gx = x0 + ((m & 7) << 1) + pj;
                s_t[m * 65 + c] = tb[(long long)c * HW + gy * W + gx];
            }
            __syncthreads();
            float acc[4][4];
            #pragma unroll
            for (int i = 0; i < 4; i++)
                #pragma unroll
                for (int j = 0; j < 4; j++) acc[i][j] = 0.f;
            #pragma unroll 8
            for (int m = 0; m < 64; m++) {
                float av[4], tv[4];
                #pragma unroll
                for (int i = 0; i < 4; i++) av[i] = s_a[(tn + 16 * i) * 65 + m];
                #pragma unroll
                for (int j = 0; j < 4; j++) tv[j] = s_t[m * 65 + tc + 16 * j];
                #pragma unroll
                for (int i = 0; i < 4; i++)
                    #pragma unroll
                    for (int j = 0; j < 4; j++) acc[i][j] = fmaf(av[i], tv[j], acc[i][j]);
            }
            #pragma unroll
            for (int i = 0; i < 4; i++) {
                int nn = tn + 16 * i;
                int gy = y0 + ((nn >> 3) << 1) + pi;
                int gx = x0 + ((nn & 7) << 1) + pj;
                #pragma unroll
                for (int j = 0; j < 4; j++)
                    outp[((long long)b * 64 + tc + 16 * j) * HW + gy * W + gx] = acc[i][j];
            }
        }
    }
}

// ---------------------------------------------------------------------------
// 3x3 conv, Cin=192 (three 64-channel inputs), Cout=64, SAME, fused bias+lrelu.
// CTA = 16x16 pixel tile x 64 couts for one batch image. 8 cin per smem chunk.
// Thread: 8 pixels x 8 couts register tile.
// ---------------------------------------------------------------------------
__global__ __launch_bounds__(256, 2)
void conv_kernel(const float* __restrict__ in0, const float* __restrict__ in1,
                 const float* __restrict__ in2,
                 const float* __restrict__ wgt, const float* __restrict__ bias,
                 float* __restrict__ outp, int H, int W) {
    __shared__ float s_in[8 * 324];   // 8 ci x 18x18 halo tile
    __shared__ float s_w[64 * 72];    // 64 couts x (8 ci x 9 taps)
    const int tid = threadIdx.x;
    const int b = blockIdx.y;
    const int ntx = W >> 4;
    const int ty0 = (blockIdx.x / ntx) << 4;
    const int tx0 = (blockIdx.x - (blockIdx.x / ntx) * ntx) << 4;
    const long long HW = (long long)H * W;
    const int lane = tid & 31, warp = tid >> 5;
    int py[8], px[8];
    #pragma unroll
    for (int i = 0; i < 8; i++) { int p = lane + 32 * i; py[i] = p >> 4; px[i] = p & 15; }
    float acc[8][8];
    #pragma unroll
    for (int j = 0; j < 8; j++)
        #pragma unroll
        for (int i = 0; i < 8; i++) acc[j][i] = 0.f;

    const float* bufs[3] = {in0, in1, in2};
    for (int ch = 0; ch < 24; ch++) {
        int cbase = ch * 8;
        const float* inp = bufs[cbase >> 6] + ((long long)b * 64 + (cbase & 63)) * HW;
        __syncthreads();
        for (int idx = tid; idx < 8 * 324; idx += 256) {
            int ci = idx / 324, r = idx - ci * 324;
            int iy = r / 18, ix = r - iy * 18;
            int gy = ty0 + iy - 1, gx = tx0 + ix - 1;
            float v = 0.f;
            if (gy >= 0 && gy < H && gx >= 0 && gx < W)
                v = inp[(long long)ci * HW + gy * W + gx];
            s_in[idx] = v;
        }
        for (int idx = tid; idx < 64 * 72; idx += 256) {
            int o = idx / 72, r = idx - o * 72;
            s_w[idx] = wgt[(long long)o * 1728 + cbase * 9 + r];
        }
        __syncthreads();
        #pragma unroll 2
        for (int ci = 0; ci < 8; ci++) {
            #pragma unroll
            for (int ky = 0; ky < 3; ky++) {
                #pragma unroll
                for (int kx = 0; kx < 3; kx++) {
                    float iv[8];
                    #pragma unroll
                    for (int i = 0; i < 8; i++)
                        iv[i] = s_in[ci * 324 + (py[i] + ky) * 18 + (px[i] + kx)];
                    #pragma unroll
                    for (int j = 0; j < 8; j++) {
                        float wv = s_w[(warp * 8 + j) * 72 + ci * 9 + ky * 3 + kx];
                        #pragma unroll
                        for (int i = 0; i < 8; i++) acc[j][i] = fmaf(wv, iv[i], acc[j][i]);
                    }
                }
            }
        }
    }
    #pragma unroll
    for (int j = 0; j < 8; j++) {
        int o = warp * 8 + j;
        float bv = bias[o];
        #pragma unroll
        for (int i = 0; i < 8; i++) {
            float v = acc[j][i] + bv;
            v = (v > 0.f) ? v : 0.1f * v;               // leaky relu 0.1
            outp[((long long)b * 64 + o) * HW + (ty0 + py[i]) * W + (tx0 + px[i])] = v;
        }
    }
}

// ---------------------------------------------------------------------------
// 2x bilinear upsample, jax.image.resize half-pixel convention (c = i/2 - 0.25),
// edge handling via index clamping. Optional fused lrelu on input.
// ---------------------------------------------------------------------------
template<bool LRELU_IN>
__global__ void upsample_kernel(const float* __restrict__ in, float* __restrict__ out,
                                int BC, int H, int W) {
    const int W2 = W * 2, H2 = H * 2;
    long long total = (long long)BC * H2 * W2;
    long long idx = (long long)blockIdx.x * 256 + threadIdx.x;
    if (idx >= total) return;
    int x = (int)(idx % W2);
    int y = (int)((idx / W2) % H2);
    int p = (int)(idx / ((long long)W2 * H2));
    float cy = 0.5f * y - 0.25f;
    float cx = 0.5f * x - 0.25f;
    int iy = (int)floorf(cy), ix = (int)floorf(cx);
    float wy = cy - iy, wx = cx - ix;
    int ya = iy < 0 ? 0 : iy;            int yb = (iy + 1 > H - 1) ? H - 1 : iy + 1;
    int xa = ix < 0 ? 0 : ix;            int xb = (ix + 1 > W - 1) ? W - 1 : ix + 1;
    const float* ip = in + (long long)p * H * W;
    float v00 = ip[ya * W + xa], v01 = ip[ya * W + xb];
    float v10 = ip[yb * W + xa], v11 = ip[yb * W + xb];
    if (LRELU_IN) {
        v00 = (v00 > 0.f) ? v00 : 0.1f * v00;
        v01 = (v01 > 0.f) ? v01 : 0.1f * v01;
        v10 = (v10 > 0.f) ? v10 : 0.1f * v10;
        v11 = (v11 > 0.f) ? v11 : 0.1f * v11;
    }
    out[idx] = (1.f - wy) * ((1.f - wx) * v00 + wx * v01)
             + wy * ((1.f - wx) * v10 + wx * v11);
}

// ---------------------------------------------------------------------------
extern "C" void kernel_launch(void* const* d_in, const int* in_sizes, int n_in,
                              void* d_out, int out_size) {
    const float* ref1 = (const float*)d_in[0];
    const float* ref2 = (const float*)d_in[1];
    const float* ref3 = (const float*)d_in[2];
    const float* ta1  = (const float*)d_in[3];
    const float* ta2  = (const float*)d_in[4];
    const float* ta3  = (const float*)d_in[5];
    const float* q_w  = (const float*)d_in[6];
    const float* q_b  = (const float*)d_in[7];
    const float* k_w  = (const float*)d_in[8];
    const float* k_b  = (const float*)d_in[9];
    const float* v_w  = (const float*)d_in[10];
    const float* v_b  = (const float*)d_in[11];
    const float* p_w  = (const float*)d_in[12];
    const float* p_b  = (const float*)d_in[13];
    const float* btab = (const float*)d_in[14];
    const float* fc_w = (const float*)d_in[15];
    const float* fc_b = (const float*)d_in[16];
    float* outp = (float*)d_out;

    void* p;
    cudaGetSymbolAddress(&p, g_mask);    float* mask = (float*)p;
    cudaGetSymbolAddress(&p, g_att3m);   float* att3 = (float*)p;
    cudaGetSymbolAddress(&p, g_att2m);   float* att2 = (float*)p;
    cudaGetSymbolAddress(&p, g_aligned); float* alig = (float*)p;
    cudaGetSymbolAddress(&p, g_up);      float* up   = (float*)p;
    cudaGetSymbolAddress(&p, g_atrans);  float* atr  = (float*)p;
    cudaGetSymbolAddress(&p, g_feat);    float* feat = (float*)p;

    cudaFuncSetAttribute(attn_kernel<true>,  cudaFuncAttributeMaxDynamicSharedMemorySize, ATTN_SMEM);
    cudaFuncSetAttribute(attn_kernel<false>, cudaFuncAttributeMaxDynamicSharedMemorySize, ATTN_SMEM);

    // ---- scale 3 (64x64), params j=2 ----
    mask_kernel<<<(4*64*64 + 255)/256, 256>>>(ref3, mask, 4*64*64, 64*64);
    attn_kernel<true><<<256, 256, ATTN_SMEM>>>(ref3, ta3, mask,
        q_w + 2*4096, q_b + 2*64, k_w + 2*4096, k_b + 2*64,
        v_w + 2*4096, v_b + 2*64, p_w + 2*4096, p_b + 2*64,
        btab + 2*900, feat, att3, 64, 64);
    upsample_kernel<true><<<(4*64*128*128 + 255)/256, 256>>>(feat, up, 256, 64, 64);

    // ---- scale 2 (128x128), params j=1 ----
    mask_kernel<<<(4*128*128 + 255)/256, 256>>>(ref2, mask, 4*128*128, 128*128);
    attn_kernel<true><<<1024, 256, ATTN_SMEM>>>(ref2, ta2, mask,
        q_w + 4096, q_b + 64, k_w + 4096, k_b + 64,
        v_w + 4096, v_b + 64, p_w + 4096, p_b + 64,
        btab + 900, alig, att2, 128, 128);
    atrans_kernel<<<256, 256>>>(ta2, att3, atr, 128, 128);
    conv_kernel<<<dim3(64, 4), 256>>>(alig, up, atr, fc_w + 110592, fc_b + 64, feat, 128, 128);
    upsample_kernel<false><<<(4*64*256*256 + 255)/256, 256>>>(feat, up, 256, 128, 128);

    // ---- scale 1 (256x256), params j=0 ----
    mask_kernel<<<(4*256*256 + 255)/256, 256>>>(ref1, mask, 4*256*256, 256*256);
    attn_kernel<false><<<4096, 256, ATTN_SMEM>>>(ref1, ta1, mask,
        q_w, q_b, k_w, k_b, v_w, v_b, p_w, p_b,
        btab, alig, (float*)0, 256, 256);
    atrans_kernel<<<1024, 256>>>(ta1, att2, atr, 256, 256);
    conv_kernel<<<dim3(256, 4), 256>>>(alig, up, atr, fc_w, fc_b, outp, 256, 256);
}

// round 3
// speedup vs baseline: 1.5937x; 1.5937x over previous
#include <cuda_runtime.h>
#include <math.h>

// ---------------------------------------------------------------------------
// MultiCrossAlign: 3-scale windowed cross-attention + attention transfer +
// fusion convs. Attention fp32; convs tf32 tensor-core (mma.sync m16n8k8).
// Scratch in __device__ globals (no allocations).
// ---------------------------------------------------------------------------

static const int ATTN_SMEM = (4*64*65 + 64 + 900 + 64) * (int)sizeof(float); // 70,672 B

__device__ float g_mask  [4*256*256];       // per-scale exposure mask (reused)
__device__ float g_att3m [256*4096];        // head-mean attention, scale 3
__device__ float g_att2m [1024*4096];       // head-mean attention, scale 2
__device__ float g_aligned[4*64*256*256];   // aligned feature (max scale)
__device__ float g_up    [4*64*256*256];    // upsampled feature
__device__ float g_atrans[4*64*256*256];    // attention-transferred feature
__device__ float g_feat  [4*64*128*128];    // small intermediate (<=128^2)

__device__ __forceinline__ unsigned f2tf(float x) {
    unsigned r; asm("cvt.rna.tf32.f32 %0, %1;" : "=r"(r) : "f"(x)); return r;
}

// ---------------------------------------------------------------------------
// mask[b,y,x] = mean_c( ref[b,c,y,x] > 0.95 ? 0 : 1 )
// ---------------------------------------------------------------------------
__global__ void mask_kernel(const float* __restrict__ ref, float* __restrict__ mask,
                            int total, int HW) {
    int idx = blockIdx.x * 256 + threadIdx.x;
    if (idx >= total) return;
    int b = idx / HW;
    int p = idx - b * HW;
    const float* r = ref + (long long)b * 64 * HW + p;
    float s = 0.f;
    #pragma unroll
    for (int c = 0; c < 64; c++) s += (r[(long long)c * HW] > 0.95f) ? 0.f : 1.f;
    mask[idx] = s * (1.f / 64.f);
}

// ---------------------------------------------------------------------------
// 64x64x64 GEMM in shared memory: out[n][c] = sum_cc in[n][cc]*w[c][cc] + b[c].
// In-place safe: __syncthreads() between compute and store.
// ---------------------------------------------------------------------------
__device__ __forceinline__ void gemm64(const float* __restrict__ s_in,
                                       const float* __restrict__ gw,
                                       const float* __restrict__ gb,
                                       float* s_w, float* s_bvec, float* s_out,
                                       int tid, float scale) {
    __syncthreads();
    #pragma unroll 4
    for (int idx = tid; idx < 4096; idx += 256) {
        int c = idx >> 6, cc = idx & 63;
        s_w[cc * 65 + c] = gw[idx];          // transpose on store
    }
    if (tid < 64) s_bvec[tid] = gb[tid];
    __syncthreads();
    const int tn = tid & 15, tc = tid >> 4;
    float acc[4][4];
    #pragma unroll
    for (int j = 0; j < 4; j++) {
        float bv = s_bvec[tc + 16 * j];
        #pragma unroll
        for (int i = 0; i < 4; i++) acc[i][j] = bv;
    }
    #pragma unroll 8
    for (int cc = 0; cc < 64; cc++) {
        float xv[4], wv[4];
        #pragma unroll
        for (int i = 0; i < 4; i++) xv[i] = s_in[(tn + 16 * i) * 65 + cc];
        #pragma unroll
        for (int j = 0; j < 4; j++) wv[j] = s_w[cc * 65 + tc + 16 * j];
        #pragma unroll
        for (int i = 0; i < 4; i++)
            #pragma unroll
            for (int j = 0; j < 4; j++) acc[i][j] = fmaf(xv[i], wv[j], acc[i][j]);
    }
    __syncthreads();   // all reads of s_in complete -> in-place output is safe
    #pragma unroll
    for (int i = 0; i < 4; i++)
        #pragma unroll
        for (int j = 0; j < 4; j++)
            s_out[(tn + 16 * i) * 65 + tc + 16 * j] = acc[i][j] * scale;
    __syncthreads();
}

// ---------------------------------------------------------------------------
// Fused windowed cross-attention. One CTA per 8x8 window, 256 threads.
// 4 tile buffers (70.7KB) -> 2 CTAs/SM.
// Buffer life: T0 = x -> K -> proj-out; T1 = y -> V (in place);
//             T2 = weight staging / att accumulator; T3 = Q -> attnV.
// ---------------------------------------------------------------------------
template<bool WRITE_ATT>
__global__ __launch_bounds__(256, 2)
void attn_kernel(const float* __restrict__ ref, const float* __restrict__ ta,
                 const float* __restrict__ mask,
                 const float* __restrict__ qw, const float* __restrict__ qb,
                 const float* __restrict__ kw, const float* __restrict__ kb,
                 const float* __restrict__ vw, const float* __restrict__ vb,
                 const float* __restrict__ pw, const float* __restrict__ pb,
                 const float* __restrict__ btab,
                 float* __restrict__ outp, float* __restrict__ attm,
                 int H, int W) {
    extern __shared__ float sm[];
    float* T0     = sm;
    float* T1     = T0 + 64 * 65;
    float* T2     = T1 + 64 * 65;
    float* T3     = T2 + 64 * 65;
    float* s_mw   = T3 + 64 * 65;     // [64] window mask
    float* s_bias = s_mw + 64;        // [225][4] relative bias table
    float* s_bvec = s_bias + 900;     // [64] bias vector

    const int tid = threadIdx.x;
    const int nwx = W >> 3;
    const int winsb = (H >> 3) * nwx;
    const int wi = blockIdx.x;
    const int b = wi / winsb;
    const int rr = wi - b * winsb;
    const int y0 = (rr / nwx) << 3;
    const int x0 = (rr - (rr / nwx) * nwx) << 3;
    const long long HW = (long long)H * W;
    const float* refb = ref + (long long)b * 64 * HW;
    const float* tab  = ta + (long long)b * 64 * HW;
    const float* mb   = mask + (long long)b * HW;

    #pragma unroll 4
    for (int idx = tid; idx < 4096; idx += 256) {
        int c = idx >> 6, n = idx & 63;
        int y = y0 + (n >> 3), x = x0 + (n & 7);
        long long g = (long long)c * HW + y * W + x;
        float m = mb[y * W + x];
        T0[n * 65 + c] = refb[g] * m;    // x = ref * mask
        T1[n * 65 + c] = tab[g];
    }
    if (tid < 64) s_mw[tid] = mb[(y0 + (tid >> 3)) * W + x0 + (tid & 7)];
    for (int i = tid; i < 900; i += 256) s_bias[i] = btab[i];

    gemm64(T0, qw, qb, T2, s_bvec, T3, tid, 0.25f);  // Q (scale = hd^-0.5)
    gemm64(T1, kw, kb, T2, s_bvec, T0, tid, 1.f);    // K
    gemm64(T1, vw, vb, T2, s_bvec, T1, tid, 1.f);    // V (in place)

    const int h = tid >> 6;
    const int n = tid & 63;
    float qr[16];
    #pragma unroll
    for (int d = 0; d < 16; d++) qr[d] = T3[n * 65 + h * 16 + d];
    const float mwn = s_mw[n];
    const int yn = n >> 3, xn = n & 7;
    float a[64];
    #pragma unroll
    for (int m = 0; m < 64; m++) {
        float s = 0.f;
        #pragma unroll
        for (int d = 0; d < 16; d++) s = fmaf(qr[d], T0[m * 65 + h * 16 + d], s);
        int ym = m >> 3, xm = m & 7;
        int rel = (yn - ym + 7) * 15 + (xn - xm + 7);
        a[m] = s * (mwn * s_mw[m]) + s_bias[rel * 4 + h];
    }
    // softmax over the register row
    float mx = a[0];
    #pragma unroll
    for (int m = 1; m < 64; m++) mx = fmaxf(mx, a[m]);
    float ssum = 0.f;
    #pragma unroll
    for (int m = 0; m < 64; m++) { a[m] = __expf(a[m] - mx); ssum += a[m]; }
    float inv = 1.f / ssum;
    #pragma unroll
    for (int m = 0; m < 64; m++) a[m] *= inv;

    if (WRITE_ATT) {
        // accumulate head-mean attention into T2 (serialized over heads)
        #pragma unroll
        for (int hh = 0; hh < 4; hh++) {
            if (h == hh) {
                if (hh == 0) {
                    #pragma unroll
                    for (int m = 0; m < 64; m++) T2[n * 65 + m] = 0.25f * a[m];
                } else {
                    #pragma unroll
                    for (int m = 0; m < 64; m++) T2[n * 65 + m] += 0.25f * a[m];
                }
            }
            __syncthreads();
        }
        float* ap = attm + (long long)wi * 4096;
        #pragma unroll 4
        for (int idx = tid; idx < 4096; idx += 256)
            ap[idx] = T2[(idx >> 6) * 65 + (idx & 63)];
    }

    // out_h = attn @ V_h (16 values per thread)
    float o16[16];
    #pragma unroll
    for (int d = 0; d < 16; d++) o16[d] = 0.f;
    #pragma unroll
    for (int m = 0; m < 64; m++) {
        float am = a[m];
        #pragma unroll
        for (int d = 0; d < 16; d++) o16[d] = fmaf(am, T1[m * 65 + h * 16 + d], o16[d]);
    }
    __syncthreads();   // all qr/score/PV reads of T3 done before overwrite
    #pragma unroll
    for (int d = 0; d < 16; d++) T3[n * 65 + h * 16 + d] = o16[d];

    gemm64(T3, pw, pb, T2, s_bvec, T0, tid, 1.f);    // output projection

    float* ob = outp + (long long)b * 64 * HW;
    #pragma unroll 4
    for (int idx = tid; idx < 4096; idx += 256) {
        int c = idx >> 6, n2 = idx & 63;
        ob[(long long)c * HW + (y0 + (n2 >> 3)) * W + x0 + (n2 & 7)] = T0[n2 * 65 + c];
    }
}

// ---------------------------------------------------------------------------
// Attention transfer: out_window = mean_h(att) @ reshaped ta window.
// One CTA per 16x16 window; 4 GEMMs of 64x64x64 (one per (pi,pj) sub-pixel).
// ---------------------------------------------------------------------------
__global__ __launch_bounds__(256)
void atrans_kernel(const float* __restrict__ ta, const float* __restrict__ attm,
                   float* __restrict__ outp, int H, int W) {
    __shared__ float s_a[64 * 65];
    __shared__ float s_t[64 * 65];
    const int tid = threadIdx.x;
    const int nwx = W >> 4;
    const int winsb = (H >> 4) * nwx;
    const int wi = blockIdx.x;
    const int b = wi / winsb;
    const int rr = wi - b * winsb;
    const int y0 = (rr / nwx) << 4;
    const int x0 = (rr - (rr / nwx) * nwx) << 4;
    const long long HW = (long long)H * W;
    const float* tb = ta + (long long)b * 64 * HW;

    for (int idx = tid; idx < 4096; idx += 256)
        s_a[(idx >> 6) * 65 + (idx & 63)] = attm[(long long)wi * 4096 + idx];

    const int tn = tid & 15, tc = tid >> 4;
    #pragma unroll
    for (int pi = 0; pi < 2; pi++) {
        #pragma unroll
        for (int pj = 0; pj < 2; pj++) {
            __syncthreads();
            for (int idx = tid; idx < 4096; idx += 256) {
                int c = idx >> 6, m = idx & 63;
                int gy = y0 + ((m >> 3) << 1) + pi;
                int gx = x0 + ((m & 7) << 1) + pj;
                s_t[m * 65 + c] = tb[(long long)c * HW + gy * W + gx];
            }
            __syncthreads();
            float acc[4][4];
            #pragma unroll
            for (int i = 0; i < 4; i++)
                #pragma unroll
                for (int j = 0; j < 4; j++) acc[i][j] = 0.f;
            #pragma unroll 8
            for (int m = 0; m < 64; m++) {
                float av[4], tv[4];
                #pragma unroll
                for (int i = 0; i < 4; i++) av[i] = s_a[(tn + 16 * i) * 65 + m];
                #pragma unroll
                for (int j = 0; j < 4; j++) tv[j] = s_t[m * 65 + tc + 16 * j];
                #pragma unroll
                for (int i = 0; i < 4; i++)
                    #pragma unroll
                    for (int j = 0; j < 4; j++) acc[i][j] = fmaf(av[i], tv[j], acc[i][j]);
            }
            #pragma unroll
            for (int i = 0; i < 4; i++) {
                int nn = tn + 16 * i;
                int gy = y0 + ((nn >> 3) << 1) + pi;
                int gx = x0 + ((nn & 7) << 1) + pj;
                #pragma unroll
                for (int j = 0; j < 4; j++)
                    outp[((long long)b * 64 + tc + 16 * j) * HW + gy * W + gx] = acc[i][j];
            }
        }
    }
}

// ---------------------------------------------------------------------------
// 3x3 conv, Cin=192 (three 64-channel inputs), Cout=64, SAME, bias+lrelu,
// via tf32 mma.sync.m16n8k8 implicit GEMM.
// CTA: 16x16 pixel tile (M=256) x 64 couts (N), K-chunks of 8 ci x 9 taps.
// Warps: 4(M) x 2(N); per-warp 4x4 grid of m16n8 accumulators.
// ---------------------------------------------------------------------------
__global__ __launch_bounds__(256, 2)
void conv_mma_kernel(const float* __restrict__ in0, const float* __restrict__ in1,
                     const float* __restrict__ in2,
                     const float* __restrict__ wgt, const float* __restrict__ bias,
                     float* __restrict__ outp, int H, int W) {
    __shared__ unsigned s_in[8 * 328];     // 8 ci x 18x18 halo (tf32), stride 328
    __shared__ unsigned s_w[9 * 8 * 72];   // [tap][k(8)][n(64), stride 72] (tf32)
    const int tid = threadIdx.x;
    const int b = blockIdx.y;
    const int ntx = W >> 4;
    const int ty0 = (blockIdx.x / ntx) << 4;
    const int tx0 = (blockIdx.x - (blockIdx.x / ntx) * ntx) << 4;
    const long long HW = (long long)H * W;
    const int lane = tid & 31, warp = tid >> 5;
    const int wm = warp & 3, wn = warp >> 2;      // warp tile: M=64, N=32
    const int g = lane >> 2, t = lane & 3;

    float acc[4][4][4];   // [mt][nt][cfrag]
    #pragma unroll
    for (int i = 0; i < 4; i++)
        #pragma unroll
        for (int j = 0; j < 4; j++)
            #pragma unroll
            for (int c = 0; c < 4; c++) acc[i][j][c] = 0.f;

    const float* bufs[3] = {in0, in1, in2};
    for (int ch = 0; ch < 24; ch++) {
        const int cbase = ch * 8;
        const float* inp = bufs[cbase >> 6] + ((long long)b * 64 + (cbase & 63)) * HW;
        __syncthreads();
        for (int idx = tid; idx < 8 * 324; idx += 256) {
            int ci = idx / 324, r = idx - ci * 324;
            int iy = r / 18, ix = r - iy * 18;
            int gy = ty0 + iy - 1, gx = tx0 + ix - 1;
            float v = 0.f;
            if (gy >= 0 && gy < H && gx >= 0 && gx < W)
                v = inp[(long long)ci * HW + gy * W + gx];
            s_in[ci * 328 + r] = f2tf(v);
        }
        for (int idx = tid; idx < 4608; idx += 256) {
            int tap = idx % 9; int rest = idx / 9;
            int k = rest & 7;  int n = rest >> 3;
            float v = wgt[(long long)n * 1728 + (cbase + k) * 9 + tap];
            s_w[tap * 576 + k * 72 + n] = f2tf(v);
        }
        __syncthreads();
        #pragma unroll
        for (int tap = 0; tap < 9; tap++) {
            const int ky = tap / 3, kx = tap - (tap / 3) * 3;
            unsigned bf0[4], bf1[4];
            #pragma unroll
            for (int nt = 0; nt < 4; nt++) {
                int nn = wn * 32 + nt * 8 + g;
                bf0[nt] = s_w[tap * 576 + t * 72 + nn];
                bf1[nt] = s_w[tap * 576 + (t + 4) * 72 + nn];
            }
            #pragma unroll
            for (int mt = 0; mt < 4; mt++) {
                int py = wm * 4 + mt;                 // tile row of this m16 tile
                int rowoff = (py + ky) * 18 + kx;
                unsigned a0 = s_in[t * 328 + rowoff + g];
                unsigned a1 = s_in[t * 328 + rowoff + g + 8];
                unsigned a2 = s_in[(t + 4) * 328 + rowoff + g];
                unsigned a3 = s_in[(t + 4) * 328 + rowoff + g + 8];
                #pragma unroll
                for (int nt = 0; nt < 4; nt++) {
                    asm volatile(
                        "mma.sync.aligned.m16n8k8.row.col.f32.tf32.tf32.f32 "
                        "{%0,%1,%2,%3}, {%4,%5,%6,%7}, {%8,%9}, {%0,%1,%2,%3};"
                        : "+f"(acc[mt][nt][0]), "+f"(acc[mt][nt][1]),
                          "+f"(acc[mt][nt][2]), "+f"(acc[mt][nt][3])
                        : "r"(a0), "r"(a1), "r"(a2), "r"(a3),
                          "r"(bf0[nt]), "r"(bf1[nt]));
                }
            }
        }
    }
    // epilogue: bias + leaky relu + NCHW store
    #pragma unroll
    for (int mt = 0; mt < 4; mt++) {
        int gy = ty0 + wm * 4 + mt;
        #pragma unroll
        for (int nt = 0; nt < 4; nt++) {
            int o = wn * 32 + nt * 8 + 2 * t;
            float bv0 = bias[o], bv1 = bias[o + 1];
            float v;
            long long base0 = ((long long)b * 64 + o) * HW + gy * W + tx0;
            long long base1 = ((long long)b * 64 + o + 1) * HW + gy * W + tx0;
            v = acc[mt][nt][0] + bv0; v = (v > 0.f) ? v : 0.1f * v; outp[base0 + g] = v;
            v = acc[mt][nt][1] + bv1; v = (v > 0.f) ? v : 0.1f * v; outp[base1 + g] = v;
            v = acc[mt][nt][2] + bv0; v = (v > 0.f) ? v : 0.1f * v; outp[base0 + g + 8] = v;
            v = acc[mt][nt][3] + bv1; v = (v > 0.f) ? v : 0.1f * v; outp[base1 + g + 8] = v;
        }
    }
}

// ---------------------------------------------------------------------------
// 2x bilinear upsample, jax.image.resize half-pixel convention (c = i/2 - 0.25),
// edge handling via index clamping. Optional fused lrelu on input.
// ---------------------------------------------------------------------------
template<bool LRELU_IN>
__global__ void upsample_kernel(const float* __restrict__ in, float* __restrict__ out,
                                int BC, int H, int W) {
    const int W2 = W * 2, H2 = H * 2;
    long long total = (long long)BC * H2 * W2;
    long long idx = (long long)blockIdx.x * 256 + threadIdx.x;
    if (idx >= total) return;
    int x = (int)(idx % W2);
    int y = (int)((idx / W2) % H2);
    int p = (int)(idx / ((long long)W2 * H2));
    float cy = 0.5f * y - 0.25f;
    float cx = 0.5f * x - 0.25f;
    int iy = (int)floorf(cy), ix = (int)floorf(cx);
    float wy = cy - iy, wx = cx - ix;
    int ya = iy < 0 ? 0 : iy;            int yb = (iy + 1 > H - 1) ? H - 1 : iy + 1;
    int xa = ix < 0 ? 0 : ix;            int xb = (ix + 1 > W - 1) ? W - 1 : ix + 1;
    const float* ip = in + (long long)p * H * W;
    float v00 = ip[ya * W + xa], v01 = ip[ya * W + xb];
    float v10 = ip[yb * W + xa], v11 = ip[yb * W + xb];
    if (LRELU_IN) {
        v00 = (v00 > 0.f) ? v00 : 0.1f * v00;
        v01 = (v01 > 0.f) ? v01 : 0.1f * v01;
        v10 = (v10 > 0.f) ? v10 : 0.1f * v10;
        v11 = (v11 > 0.f) ? v11 : 0.1f * v11;
    }
    out[idx] = (1.f - wy) * ((1.f - wx) * v00 + wx * v01)
             + wy * ((1.f - wx) * v10 + wx * v11);
}

// ---------------------------------------------------------------------------
extern "C" void kernel_launch(void* const* d_in, const int* in_sizes, int n_in,
                              void* d_out, int out_size) {
    const float* ref1 = (const float*)d_in[0];
    const float* ref2 = (const float*)d_in[1];
    const float* ref3 = (const float*)d_in[2];
    const float* ta1  = (const float*)d_in[3];
    const float* ta2  = (const float*)d_in[4];
    const float* ta3  = (const float*)d_in[5];
    const float* q_w  = (const float*)d_in[6];
    const float* q_b  = (const float*)d_in[7];
    const float* k_w  = (const float*)d_in[8];
    const float* k_b  = (const float*)d_in[9];
    const float* v_w  = (const float*)d_in[10];
    const float* v_b  = (const float*)d_in[11];
    const float* p_w  = (const float*)d_in[12];
    const float* p_b  = (const float*)d_in[13];
    const float* btab = (const float*)d_in[14];
    const float* fc_w = (const float*)d_in[15];
    const float* fc_b = (const float*)d_in[16];
    float* outp = (float*)d_out;

    void* p;
    cudaGetSymbolAddress(&p, g_mask);    float* mask = (float*)p;
    cudaGetSymbolAddress(&p, g_att3m);   float* att3 = (float*)p;
    cudaGetSymbolAddress(&p, g_att2m);   float* att2 = (float*)p;
    cudaGetSymbolAddress(&p, g_aligned); float* alig = (float*)p;
    cudaGetSymbolAddress(&p, g_up);      float* up   = (float*)p;
    cudaGetSymbolAddress(&p, g_atrans);  float* atr  = (float*)p;
    cudaGetSymbolAddress(&p, g_feat);    float* feat = (float*)p;

    cudaFuncSetAttribute(attn_kernel<true>,  cudaFuncAttributeMaxDynamicSharedMemorySize, ATTN_SMEM);
    cudaFuncSetAttribute(attn_kernel<false>, cudaFuncAttributeMaxDynamicSharedMemorySize, ATTN_SMEM);

    // ---- scale 3 (64x64), params j=2 ----
    mask_kernel<<<(4*64*64 + 255)/256, 256>>>(ref3, mask, 4*64*64, 64*64);
    attn_kernel<true><<<256, 256, ATTN_SMEM>>>(ref3, ta3, mask,
        q_w + 2*4096, q_b + 2*64, k_w + 2*4096, k_b + 2*64,
        v_w + 2*4096, v_b + 2*64, p_w + 2*4096, p_b + 2*64,
        btab + 2*900, feat, att3, 64, 64);
    upsample_kernel<true><<<(4*64*128*128 + 255)/256, 256>>>(feat, up, 256, 64, 64);

    // ---- scale 2 (128x128), params j=1 ----
    mask_kernel<<<(4*128*128 + 255)/256, 256>>>(ref2, mask, 4*128*128, 128*128);
    attn_kernel<true><<<1024, 256, ATTN_SMEM>>>(ref2, ta2, mask,
        q_w + 4096, q_b + 64, k_w + 4096, k_b + 64,
        v_w + 4096, v_b + 64, p_w + 4096, p_b + 64,
        btab + 900, alig, att2, 128, 128);
    atrans_kernel<<<256, 256>>>(ta2, att3, atr, 128, 128);
    conv_mma_kernel<<<dim3(64, 4), 256>>>(alig, up, atr, fc_w + 110592, fc_b + 64, feat, 128, 128);
    upsample_kernel<false><<<(4*64*256*256 + 255)/256, 256>>>(feat, up, 256, 128, 128);

    // ---- scale 1 (256x256), params j=0 ----
    mask_kernel<<<(4*256*256 + 255)/256, 256>>>(ref1, mask, 4*256*256, 256*256);
    attn_kernel<false><<<4096, 256, ATTN_SMEM>>>(ref1, ta1, mask,
        q_w, q_b, k_w, k_b, v_w, v_b, p_w, p_b,
        btab, alig, (float*)0, 256, 256);
    atrans_kernel<<<1024, 256>>>(ta1, att2, atr, 256, 256);
    conv_mma_kernel<<<dim3(256, 4), 256>>>(alig, up, atr, fc_w, fc_b, outp, 256, 256);
}

// round 5
// speedup vs baseline: 1.7812x; 1.1177x over previous
#include <cuda_runtime.h>
#include <math.h>

// ---------------------------------------------------------------------------
// MultiCrossAlign: 3-scale windowed cross-attention + attention transfer +
// fusion convs. tf32 tensor cores for all GEMM-shaped work; fp32 softmax.
// Scratch in __device__ globals (no allocations).
// ---------------------------------------------------------------------------

// attn smem: T0,T1,T3 data tiles (64x68) + T2 weight tile (64x72) + extras
static const int ATTN_SMEM = (3*64*68 + 64*72 + 64 + 900 + 64) * (int)sizeof(float); // 74,768B

__device__ float g_mask  [4*(4096 + 16384 + 65536)];   // masks for scales 3,2,1
__device__ float g_att3m [256*4096];        // head-mean attention, scale 3
__device__ float g_att2m [1024*4096];       // head-mean attention, scale 2
__device__ float g_aligned[4*64*256*256];   // aligned feature (max scale)
__device__ float g_up    [4*64*256*256];    // upsampled feature
__device__ float g_atrans[4*64*256*256];    // attention-transferred feature
__device__ float g_feat  [4*64*128*128];    // small intermediate (<=128^2)

__device__ __forceinline__ unsigned f2tf(float x) {
    unsigned r; asm("cvt.rna.tf32.f32 %0, %1;" : "=r"(r) : "f"(x)); return r;
}

__device__ __forceinline__ void mma_tf32(float* c, unsigned a0, unsigned a1,
                                         unsigned a2, unsigned a3,
                                         unsigned b0, unsigned b1) {
    asm volatile(
        "mma.sync.aligned.m16n8k8.row.col.f32.tf32.tf32.f32 "
        "{%0,%1,%2,%3}, {%4,%5,%6,%7}, {%8,%9}, {%0,%1,%2,%3};"
        : "+f"(c[0]), "+f"(c[1]), "+f"(c[2]), "+f"(c[3])
        : "r"(a0), "r"(a1), "r"(a2), "r"(a3), "r"(b0), "r"(b1));
}

// ---------------------------------------------------------------------------
// mask[b,y,x] = mean_c( ref[b,c,y,x] > 0.95 ? 0 : 1 )
// ---------------------------------------------------------------------------
__global__ void mask_kernel(const float* __restrict__ ref, float* __restrict__ mask,
                            int total, int HW) {
    int idx = blockIdx.x * 256 + threadIdx.x;
    if (idx >= total) return;
    int b = idx / HW;
    int p = idx - b * HW;
    const float* r = ref + (long long)b * 64 * HW + p;
    float s = 0.f;
    #pragma unroll
    for (int c = 0; c < 64; c++) s += (r[(long long)c * HW] > 0.95f) ? 0.f : 1.f;
    mask[idx] = s * (1.f / 64.f);
}

// ---------------------------------------------------------------------------
// 64x64x64 GEMM via tf32 mma: s_out[n][c] = (sum_k s_in[n][k]*gw[c][k] + gb[c])*scale
// s_in/s_out stride 68 (fp32); s_w staging stride 72 (tf32). In-place safe.
// 8 warps: warp w -> m-block (w&3)*16, n-block (w>>2)*32 (4 n8-tiles).
// ---------------------------------------------------------------------------
__device__ __forceinline__ void gemm_mma(const float* __restrict__ s_in,
                                         const float* __restrict__ gw,
                                         const float* __restrict__ gb,
                                         float* s_wf, float* s_bvec, float* s_out,
                                         int tid, float scale) {
    unsigned* s_w = (unsigned*)s_wf;
    __syncthreads();
    #pragma unroll 4
    for (int idx = tid; idx < 4096; idx += 256) {
        int n = idx >> 6, k = idx & 63;
        s_w[k * 72 + n] = f2tf(gw[idx]);        // B[k][n] = w[n][k]
    }
    if (tid < 64) s_bvec[tid] = gb[tid];
    __syncthreads();
    const int lane = tid & 31, warp = tid >> 5;
    const int g = lane >> 2, t = lane & 3;
    const int mb = (warp & 3) * 16, nb = (warp >> 2) * 32;
    float acc[4][4];
    #pragma unroll
    for (int nt = 0; nt < 4; nt++) {
        int col = nb + nt * 8 + 2 * t;
        float b0 = s_bvec[col], b1 = s_bvec[col + 1];
        acc[nt][0] = b0; acc[nt][1] = b1; acc[nt][2] = b0; acc[nt][3] = b1;
    }
    #pragma unroll
    for (int ks = 0; ks < 8; ks++) {
        const int k0 = ks * 8;
        unsigned a0 = f2tf(s_in[(mb + g) * 68 + k0 + t]);
        unsigned a1 = f2tf(s_in[(mb + g + 8) * 68 + k0 + t]);
        unsigned a2 = f2tf(s_in[(mb + g) * 68 + k0 + t + 4]);
        unsigned a3 = f2tf(s_in[(mb + g + 8) * 68 + k0 + t + 4]);
        #pragma unroll
        for (int nt = 0; nt < 4; nt++) {
            unsigned b0 = s_w[(k0 + t) * 72 + nb + nt * 8 + g];
            unsigned b1 = s_w[(k0 + t + 4) * 72 + nb + nt * 8 + g];
            mma_tf32(acc[nt], a0, a1, a2, a3, b0, b1);
        }
    }
    __syncthreads();   // all reads of s_in complete -> in-place output safe
    #pragma unroll
    for (int nt = 0; nt < 4; nt++) {
        int col = nb + nt * 8 + 2 * t;
        s_out[(mb + g) * 68 + col]         = acc[nt][0] * scale;
        s_out[(mb + g) * 68 + col + 1]     = acc[nt][1] * scale;
        s_out[(mb + g + 8) * 68 + col]     = acc[nt][2] * scale;
        s_out[(mb + g + 8) * 68 + col + 1] = acc[nt][3] * scale;
    }
    __syncthreads();
}

// ---------------------------------------------------------------------------
// Fused windowed cross-attention. One CTA per 8x8 window, 256 threads,
// 2 CTAs/SM. Buffers: T0 = x -> K -> proj-out; T1 = y -> V (in place);
// T2 = tf32 weight staging / att-mean accumulator; T3 = Q -> attnV.
// ---------------------------------------------------------------------------
template<bool WRITE_ATT>
__global__ __launch_bounds__(256, 2)
void attn_kernel(const float* __restrict__ ref, const float* __restrict__ ta,
                 const float* __restrict__ mask,
                 const float* __restrict__ qw, const float* __restrict__ qb,
                 const float* __restrict__ kw, const float* __restrict__ kb,
                 const float* __restrict__ vw, const float* __restrict__ vb,
                 const float* __restrict__ pw, const float* __restrict__ pb,
                 const float* __restrict__ btab,
                 float* __restrict__ outp, float* __restrict__ attm,
                 int H, int W) {
    extern __shared__ float sm[];
    float* T0     = sm;                // stride 68
    float* T1     = T0 + 64 * 68;
    float* T3     = T1 + 64 * 68;
    float* T2     = T3 + 64 * 68;      // 64*72 weight staging / att accum
    float* s_mw   = T2 + 64 * 72;      // [64] window mask
    float* s_bias = s_mw + 64;         // [225][4] relative bias table
    float* s_bvec = s_bias + 900;      // [64] bias vector

    const int tid = threadIdx.x;
    const int nwx = W >> 3;
    const int winsb = (H >> 3) * nwx;
    const int wi = blockIdx.x;
    const int b = wi / winsb;
    const int rr = wi - b * winsb;
    const int y0 = (rr / nwx) << 3;
    const int x0 = (rr - (rr / nwx) * nwx) << 3;
    const long long HW = (long long)H * W;
    const float* refb = ref + (long long)b * 64 * HW;
    const float* tab  = ta + (long long)b * 64 * HW;
    const float* mb   = mask + (long long)b * HW;

    #pragma unroll 4
    for (int idx = tid; idx < 4096; idx += 256) {
        int c = idx >> 6, n = idx & 63;
        int y = y0 + (n >> 3), x = x0 + (n & 7);
        long long g = (long long)c * HW + y * W + x;
        float m = mb[y * W + x];
        T0[n * 68 + c] = refb[g] * m;    // x = ref * mask
        T1[n * 68 + c] = tab[g];
    }
    if (tid < 64) s_mw[tid] = mb[(y0 + (tid >> 3)) * W + x0 + (tid & 7)];
    for (int i = tid; i < 900; i += 256) s_bias[i] = btab[i];

    gemm_mma(T0, qw, qb, T2, s_bvec, T3, tid, 0.25f);  // Q (scale = hd^-0.5)
    gemm_mma(T1, kw, kb, T2, s_bvec, T0, tid, 1.f);    // K
    gemm_mma(T1, vw, vb, T2, s_bvec, T1, tid, 1.f);    // V (in place)

    const int h = tid >> 6;
    const int n = tid & 63;
    float4 q4[4];
    {
        const float4* qp = (const float4*)(T3 + n * 68 + h * 16);
        #pragma unroll
        for (int i = 0; i < 4; i++) q4[i] = qp[i];
    }
    const float mwn = s_mw[n];
    const int yn = n >> 3, xn = n & 7;
    float a[64];
    #pragma unroll
    for (int m = 0; m < 64; m++) {
        const float4* kp = (const float4*)(T0 + m * 68 + h * 16);
        float s = 0.f;
        #pragma unroll
        for (int i = 0; i < 4; i++) {
            float4 kv = kp[i];
            s = fmaf(q4[i].x, kv.x, s); s = fmaf(q4[i].y, kv.y, s);
            s = fmaf(q4[i].z, kv.z, s); s = fmaf(q4[i].w, kv.w, s);
        }
        int ym = m >> 3, xm = m & 7;
        int rel = (yn - ym + 7) * 15 + (xn - xm + 7);
        a[m] = s * (mwn * s_mw[m]) + s_bias[rel * 4 + h];
    }
    // softmax over the register row
    float mx = a[0];
    #pragma unroll
    for (int m = 1; m < 64; m++) mx = fmaxf(mx, a[m]);
    float ssum = 0.f;
    #pragma unroll
    for (int m = 0; m < 64; m++) { a[m] = __expf(a[m] - mx); ssum += a[m]; }
    float inv = 1.f / ssum;
    #pragma unroll
    for (int m = 0; m < 64; m++) a[m] *= inv;

    if (WRITE_ATT) {
        // accumulate head-mean attention into T2 [n*65+m] (serialized over heads)
        #pragma unroll
        for (int hh = 0; hh < 4; hh++) {
            if (h == hh) {
                if (hh == 0) {
                    #pragma unroll
                    for (int m = 0; m < 64; m++) T2[n * 65 + m] = 0.25f * a[m];
                } else {
                    #pragma unroll
                    for (int m = 0; m < 64; m++) T2[n * 65 + m] += 0.25f * a[m];
                }
            }
            __syncthreads();
        }
        float* ap = attm + (long long)wi * 4096;
        #pragma unroll 4
        for (int idx = tid; idx < 4096; idx += 256)
            ap[idx] = T2[(idx >> 6) * 65 + (idx & 63)];
    }

    // out_h = attn @ V_h (16 values per thread, float4 accumulators)
    float4 o4[4];
    #pragma unroll
    for (int i = 0; i < 4; i++) o4[i] = make_float4(0.f, 0.f, 0.f, 0.f);
    #pragma unroll
    for (int m = 0; m < 64; m++) {
        float am = a[m];
        const float4* vp = (const float4*)(T1 + m * 68 + h * 16);
        #pragma unroll
        for (int i = 0; i < 4; i++) {
            float4 vv = vp[i];
            o4[i].x = fmaf(am, vv.x, o4[i].x); o4[i].y = fmaf(am, vv.y, o4[i].y);
            o4[i].z = fmaf(am, vv.z, o4[i].z); o4[i].w = fmaf(am, vv.w, o4[i].w);
        }
    }
    __syncthreads();   // all reads of T3 (q) done before overwrite
    {
        float4* op = (float4*)(T3 + n * 68 + h * 16);
        #pragma unroll
        for (int i = 0; i < 4; i++) op[i] = o4[i];
    }

    gemm_mma(T3, pw, pb, T2, s_bvec, T0, tid, 1.f);    // output projection

    float* ob = outp + (long long)b * 64 * HW;
    #pragma unroll 4
    for (int idx = tid; idx < 4096; idx += 256) {
        int c = idx >> 6, n2 = idx & 63;
        ob[(long long)c * HW + (y0 + (n2 >> 3)) * W + x0 + (n2 & 7)] = T0[n2 * 68 + c];
    }
}

// ---------------------------------------------------------------------------
// Attention transfer: out_window = mean_h(att) @ reshaped ta window.
// One CTA per 16x16 window; 4 tf32-mma GEMMs of 64x64x64 (one per sub-pixel).
// ---------------------------------------------------------------------------
__global__ __launch_bounds__(256)
void atrans_kernel(const float* __restrict__ ta, const float* __restrict__ attm,
                   float* __restrict__ outp, int H, int W) {
    __shared__ float s_a[64 * 68];     // att, fp32, stride 68
    __shared__ float s_tf[64 * 72];    // ta tile, tf32, [k=m][n=c] stride 72
    unsigned* s_t = (unsigned*)s_tf;
    const int tid = threadIdx.x;
    const int nwx = W >> 4;
    const int winsb = (H >> 4) * nwx;
    const int wi = blockIdx.x;
    const int b = wi / winsb;
    const int rr = wi - b * winsb;
    const int y0 = (rr / nwx) << 4;
    const int x0 = (rr - (rr / nwx) * nwx) << 4;
    const long long HW = (long long)H * W;
    const float* tb = ta + (long long)b * 64 * HW;

    for (int idx = tid; idx < 4096; idx += 256)
        s_a[(idx >> 6) * 68 + (idx & 63)] = attm[(long long)wi * 4096 + idx];

    const int lane = tid & 31, warp = tid >> 5;
    const int g = lane >> 2, t = lane & 3;
    const int mb = (warp & 3) * 16, nb = (warp >> 2) * 32;

    #pragma unroll
    for (int pi = 0; pi < 2; pi++) {
        #pragma unroll
        for (int pj = 0; pj < 2; pj++) {
            __syncthreads();
            for (int idx = tid; idx < 4096; idx += 256) {
                int c = idx >> 6, m = idx & 63;
                int gy = y0 + ((m >> 3) << 1) + pi;
                int gx = x0 + ((m & 7) << 1) + pj;
                s_t[m * 72 + c] = f2tf(tb[(long long)c * HW + gy * W + gx]);
            }
            __syncthreads();
            float acc[4][4];
            #pragma unroll
            for (int nt = 0; nt < 4; nt++)
                #pragma unroll
                for (int q = 0; q < 4; q++) acc[nt][q] = 0.f;
            #pragma unroll
            for (int ks = 0; ks < 8; ks++) {
                const int k0 = ks * 8;
                unsigned a0 = f2tf(s_a[(mb + g) * 68 + k0 + t]);
                unsigned a1 = f2tf(s_a[(mb + g + 8) * 68 + k0 + t]);
                unsigned a2 = f2tf(s_a[(mb + g) * 68 + k0 + t + 4]);
                unsigned a3 = f2tf(s_a[(mb + g + 8) * 68 + k0 + t + 4]);
                #pragma unroll
                for (int nt = 0; nt < 4; nt++) {
                    unsigned b0 = s_t[(k0 + t) * 72 + nb + nt * 8 + g];
                    unsigned b1 = s_t[(k0 + t + 4) * 72 + nb + nt * 8 + g];
                    mma_tf32(acc[nt], a0, a1, a2, a3, b0, b1);
                }
            }
            // store C fragments directly to global (NCHW)
            #pragma unroll
            for (int nt = 0; nt < 4; nt++) {
                int col = nb + nt * 8 + 2 * t;
                int r0 = mb + g, r1 = mb + g + 8;
                int gy0 = y0 + ((r0 >> 3) << 1) + pi, gx0 = x0 + ((r0 & 7) << 1) + pj;
                int gy1 = y0 + ((r1 >> 3) << 1) + pi, gx1 = x0 + ((r1 & 7) << 1) + pj;
                outp[((long long)b * 64 + col) * HW + gy0 * W + gx0]     = acc[nt][0];
                outp[((long long)b * 64 + col + 1) * HW + gy0 * W + gx0] = acc[nt][1];
                outp[((long long)b * 64 + col) * HW + gy1 * W + gx1]     = acc[nt][2];
                outp[((long long)b * 64 + col + 1) * HW + gy1 * W + gx1] = acc[nt][3];
            }
        }
    }
}

// ---------------------------------------------------------------------------
// 3x3 conv, Cin=192 (three 64-channel inputs), Cout=64, SAME, bias+lrelu,
// via tf32 mma.sync.m16n8k8 implicit GEMM.
// ---------------------------------------------------------------------------
__global__ __launch_bounds__(256, 2)
void conv_mma_kernel(const float* __restrict__ in0, const float* __restrict__ in1,
                     const float* __restrict__ in2,
                     const float* __restrict__ wgt, const float* __restrict__ bias,
                     float* __restrict__ outp, int H, int W) {
    __shared__ unsigned s_in[8 * 328];     // 8 ci x 18x18 halo (tf32), stride 328
    __shared__ unsigned s_w[9 * 8 * 72];   // [tap][k(8)][n(64), stride 72] (tf32)
    const int tid = threadIdx.x;
    const int b = blockIdx.y;
    const int ntx = W >> 4;
    const int ty0 = (blockIdx.x / ntx) << 4;
    const int tx0 = (blockIdx.x - (blockIdx.x / ntx) * ntx) << 4;
    const long long HW = (long long)H * W;
    const int lane = tid & 31, warp = tid >> 5;
    const int wm = warp & 3, wn = warp >> 2;      // warp tile: M=64, N=32
    const int g = lane >> 2, t = lane & 3;

    float acc[4][4][4];   // [mt][nt][cfrag]
    #pragma unroll
    for (int i = 0; i < 4; i++)
        #pragma unroll
        for (int j = 0; j < 4; j++)
            #pragma unroll
            for (int c = 0; c < 4; c++) acc[i][j][c] = 0.f;

    const float* bufs[3] = {in0, in1, in2};
    for (int ch = 0; ch < 24; ch++) {
        const int cbase = ch * 8;
        const float* inp = bufs[cbase >> 6] + ((long long)b * 64 + (cbase & 63)) * HW;
        __syncthreads();
        for (int idx = tid; idx < 8 * 324; idx += 256) {
            int ci = idx / 324, r = idx - ci * 324;
            int iy = r / 18, ix = r - iy * 18;
            int gy = ty0 + iy - 1, gx = tx0 + ix - 1;
            float v = 0.f;
            if (gy >= 0 && gy < H && gx >= 0 && gx < W)
                v = inp[(long long)ci * HW + gy * W + gx];
            s_in[ci * 328 + r] = f2tf(v);
        }
        for (int idx = tid; idx < 4608; idx += 256) {
            int tap = idx % 9; int rest = idx / 9;
            int k = rest & 7;  int n = rest >> 3;
            float v = wgt[(long long)n * 1728 + (cbase + k) * 9 + tap];
            s_w[tap * 576 + k * 72 + n] = f2tf(v);
        }
        __syncthreads();
        #pragma unroll
        for (int tap = 0; tap < 9; tap++) {
            const int ky = tap / 3, kx = tap - (tap / 3) * 3;
            unsigned bf0[4], bf1[4];
            #pragma unroll
            for (int nt = 0; nt < 4; nt++) {
                int nn = wn * 32 + nt * 8 + g;
                bf0[nt] = s_w[tap * 576 + t * 72 + nn];
                bf1[nt] = s_w[tap * 576 + (t + 4) * 72 + nn];
            }
            #pragma unroll
            for (int mt = 0; mt < 4; mt++) {
                int py = wm * 4 + mt;                 // tile row of this m16 tile
                int rowoff = (py + ky) * 18 + kx;
                unsigned a0 = s_in[t * 328 + rowoff + g];
                unsigned a1 = s_in[t * 328 + rowoff + g + 8];
                unsigned a2 = s_in[(t + 4) * 328 + rowoff + g];
                unsigned a3 = s_in[(t + 4) * 328 + rowoff + g + 8];
                #pragma unroll
                for (int nt = 0; nt < 4; nt++) {
                    mma_tf32(acc[mt][nt], a0, a1, a2, a3, bf0[nt], bf1[nt]);
                }
            }
        }
    }
    // epilogue: bias + leaky relu + NCHW store
    #pragma unroll
    for (int mt = 0; mt < 4; mt++) {
        int gy = ty0 + wm * 4 + mt;
        #pragma unroll
        for (int nt = 0; nt < 4; nt++) {
            int o = wn * 32 + nt * 8 + 2 * t;
            float bv0 = bias[o], bv1 = bias[o + 1];
            float v;
            long long base0 = ((long long)b * 64 + o) * HW + gy * W + tx0;
            long long base1 = ((long long)b * 64 + o + 1) * HW + gy * W + tx0;
            v = acc[mt][nt][0] + bv0; v = (v > 0.f) ? v : 0.1f * v; outp[base0 + g] = v;
            v = acc[mt][nt][1] + bv1; v = (v > 0.f) ? v : 0.1f * v; outp[base1 + g] = v;
            v = acc[mt][nt][2] + bv0; v = (v > 0.f) ? v : 0.1f * v; outp[base0 + g + 8] = v;
            v = acc[mt][nt][3] + bv1; v = (v > 0.f) ? v : 0.1f * v; outp[base1 + g + 8] = v;
        }
    }
}

// ---------------------------------------------------------------------------
// 2x bilinear upsample, jax.image.resize half-pixel convention (c = i/2 - 0.25),
// edge handling via index clamping. Optional fused lrelu on input.
// ---------------------------------------------------------------------------
template<bool LRELU_IN>
__global__ void upsample_kernel(const float* __restrict__ in, float* __restrict__ out,
                                int BC, int H, int W) {
    const int W2 = W * 2, H2 = H * 2;
    long long total = (long long)BC * H2 * W2;
    long long idx = (long long)blockIdx.x * 256 + threadIdx.x;
    if (idx >= total) return;
    int x = (int)(idx % W2);
    int y = (int)((idx / W2) % H2);
    int p = (int)(idx / ((long long)W2 * H2));
    float cy = 0.5f * y - 0.25f;
    float cx = 0.5f * x - 0.25f;
    int iy = (int)floorf(cy), ix = (int)floorf(cx);
    float wy = cy - iy, wx = cx - ix;
    int ya = iy < 0 ? 0 : iy;            int yb = (iy + 1 > H - 1) ? H - 1 : iy + 1;
    int xa = ix < 0 ? 0 : ix;            int xb = (ix + 1 > W - 1) ? W - 1 : ix + 1;
    const float* ip = in + (long long)p * H * W;
    float v00 = ip[ya * W + xa], v01 = ip[ya * W + xb];
    float v10 = ip[yb * W + xa], v11 = ip[yb * W + xb];
    if (LRELU_IN) {
        v00 = (v00 > 0.f) ? v00 : 0.1f * v00;
        v01 = (v01 > 0.f) ? v01 : 0.1f * v01;
        v10 = (v10 > 0.f) ? v10 : 0.1f * v10;
        v11 = (v11 > 0.f) ? v11 : 0.1f * v11;
    }
    out[idx] = (1.f - wy) * ((1.f - wx) * v00 + wx * v01)
             + wy * ((1.f - wx) * v10 + wx * v11);
}

// ---------------------------------------------------------------------------
extern "C" void kernel_launch(void* const* d_in, const int* in_sizes, int n_in,
                              void* d_out, int out_size) {
    const float* ref1 = (const float*)d_in[0];
    const float* ref2 = (const float*)d_in[1];
    const float* ref3 = (const float*)d_in[2];
    const float* ta1  = (const float*)d_in[3];
    const float* ta2  = (const float*)d_in[4];
    const float* ta3  = (const float*)d_in[5];
    const float* q_w  = (const float*)d_in[6];
    const float* q_b  = (const float*)d_in[7];
    const float* k_w  = (const float*)d_in[8];
    const float* k_b  = (const float*)d_in[9];
    const float* v_w  = (const float*)d_in[10];
    const float* v_b  = (const float*)d_in[11];
    const float* p_w  = (const float*)d_in[12];
    const float* p_b  = (const float*)d_in[13];
    const float* btab = (const float*)d_in[14];
    const float* fc_w = (const float*)d_in[15];
    const float* fc_b = (const float*)d_in[16];
    float* outp = (float*)d_out;

    void* p;
    cudaGetSymbolAddress(&p, g_mask);    float* maskb = (float*)p;
    cudaGetSymbolAddress(&p, g_att3m);   float* att3 = (float*)p;
    cudaGetSymbolAddress(&p, g_att2m);   float* att2 = (float*)p;
    cudaGetSymbolAddress(&p, g_aligned); float* alig = (float*)p;
    cudaGetSymbolAddress(&p, g_up);      float* up   = (float*)p;
    cudaGetSymbolAddress(&p, g_atrans);  float* atr  = (float*)p;
    cudaGetSymbolAddress(&p, g_feat);    float* feat = (float*)p;

    float* mask3 = maskb;
    float* mask2 = maskb + 4 * 4096;
    float* mask1 = maskb + 4 * 4096 + 4 * 16384;

    cudaFuncSetAttribute(attn_kernel<true>,  cudaFuncAttributeMaxDynamicSharedMemorySize, ATTN_SMEM);
    cudaFuncSetAttribute(attn_kernel<false>, cudaFuncAttributeMaxDynamicSharedMemorySize, ATTN_SMEM);

    // masks first (independent) — also places attn at the ncu capture slot
    mask_kernel<<<(4*64*64 + 255)/256, 256>>>(ref3, mask3, 4*64*64, 64*64);
    mask_kernel<<<(4*128*128 + 255)/256, 256>>>(ref2, mask2, 4*128*128, 128*128);
    mask_kernel<<<(4*256*256 + 255)/256, 256>>>(ref1, mask1, 4*256*256, 256*256);

    // ---- scale 3 (64x64), params j=2 ----
    attn_kernel<true><<<256, 256, ATTN_SMEM>>>(ref3, ta3, mask3,
        q_w + 2*4096, q_b + 2*64, k_w + 2*4096, k_b + 2*64,
        v_w + 2*4096, v_b + 2*64, p_w + 2*4096, p_b + 2*64,
        btab + 2*900, feat, att3, 64, 64);
    upsample_kernel<true><<<(4*64*128*128 + 255)/256, 256>>>(feat, up, 256, 64, 64);

    // ---- scale 2 (128x128), params j=1 ----
    attn_kernel<true><<<1024, 256, ATTN_SMEM>>>(ref2, ta2, mask2,
        q_w + 4096, q_b + 64, k_w + 4096, k_b + 64,
        v_w + 4096, v_b + 64, p_w + 4096, p_b + 64,
        btab + 900, alig, att2, 128, 128);
    atrans_kernel<<<256, 256>>>(ta2, att3, atr, 128, 128);
    conv_mma_kernel<<<dim3(64, 4), 256>>>(alig, up, atr, fc_w + 110592, fc_b + 64, feat, 128, 128);
    upsample_kernel<false><<<(4*64*256*256 + 255)/256, 256>>>(feat, up, 256, 128, 128);

    // ---- scale 1 (256x256), params j=0 ----
    attn_kernel<false><<<4096, 256, ATTN_SMEM>>>(ref1, ta1, mask1,
        q_w, q_b, k_w, k_b, v_w, v_b, p_w, p_b,
        btab, alig, (float*)0, 256, 256);
    atrans_kernel<<<1024, 256>>>(ta1, att2, atr, 256, 256);
    conv_mma_kernel<<<dim3(256, 4), 256>>>(alig, up, atr, fc_w, fc_b, outp, 256, 256);
}